// round 16
// baseline (speedup 1.0000x reference)
#include <cuda_runtime.h>
#include <cuda_fp16.h>
#include <cuda_fp8.h>
#include <math.h>
#include <stdint.h>

#define NN 8192
#define DD 128
#define TS 128
#define NT (NN / TS)                 // 64
#define NTILES (NT * (NT + 1) / 2)   // 2080
#define SROWB 144                    // fp8 tile row stride (128 + 16 pad)
#define TILE8B (TS * SROWB)          // 18432
#define NBLK (NN / 8)
#define SCL 8.0f                     // fp8 pre-scale; sims x64

typedef unsigned long long ull;

// ---------------- device scratch ----------------
__device__ float   g_xn[NN * DD];    // fp32 normalized rows (FFMA path A)
__device__ __half  g_h[NN * DD];     // fp16 normalized rows (FFMA path B)
__device__ uint8_t g_f8[NN * DD];    // e4m3 x8 rows (tensor path)
__device__ float g_pos[NN * 3];
__device__ float g_minpos[NN];
__device__ float g_sumf[NN];
__device__ int   g_nneg[NN];
__device__ float g_Spart[NBLK * DD];

__device__ __forceinline__ uint32_t smem_u32(const void* p) {
    uint32_t a;
    asm("{ .reg .u64 t; cvta.to.shared.u64 t, %1; cvt.u32.u64 %0, t; }"
        : "=r"(a) : "l"(p));
    return a;
}

__device__ __forceinline__ void ldsm4(uint32_t r[4], uint32_t addr) {
    asm volatile("ldmatrix.sync.aligned.m8n8.x4.shared.b16 {%0,%1,%2,%3}, [%4];"
                 : "=r"(r[0]), "=r"(r[1]), "=r"(r[2]), "=r"(r[3]) : "r"(addr));
}

__device__ __forceinline__ void mma16832f8(float c[4], const uint32_t a[4],
                                           const uint32_t b[2]) {
    asm volatile(
        "mma.sync.aligned.m16n8k32.row.col.f32.e4m3.e4m3.f32 "
        "{%0,%1,%2,%3},{%4,%5,%6,%7},{%8,%9},{%0,%1,%2,%3};"
        : "+f"(c[0]), "+f"(c[1]), "+f"(c[2]), "+f"(c[3])
        : "r"(a[0]), "r"(a[1]), "r"(a[2]), "r"(a[3]), "r"(b[0]), "r"(b[1]));
}

__device__ __forceinline__ ull pk(float x, float y) {
    ull r; asm("mov.b64 %0,{%1,%2};" : "=l"(r) : "f"(x), "f"(y)); return r;
}
__device__ __forceinline__ float2 upk(ull v) {
    float2 r; asm("mov.b64 {%0,%1},%2;" : "=f"(r.x), "=f"(r.y) : "l"(v)); return r;
}
__device__ __forceinline__ void fma2(ull& d, ull a, ull b) {
    asm("fma.rn.f32x2 %0,%1,%2,%0;" : "+l"(d) : "l"(a), "l"(b));
}

// Schraudolph exp(20 s - 10); unscaled sims
__device__ __forceinline__ float fexp20(float s) {
    return __int_as_float((int)fmaf(242044064.0f, s, 943844773.0f));
}
// x64-scaled sims (tensor path)
__device__ __forceinline__ float fexp20s(float s64) {
    return __int_as_float((int)fmaf(3781938.5f, s64, 943844773.0f));
}

// ---------------- kernel 1: normalize + fp32/fp16/fp8 + positives + S partials ----------------
__global__ void prep_kernel(const float* __restrict__ x) {
    __shared__ float xs[8][128];
    int wid = threadIdx.x >> 5, lane = threadIdx.x & 31;
    int row = blockIdx.x * 8 + wid;

    float4 v = ((const float4*)(x + (size_t)row * DD))[lane];
    float ss = v.x*v.x + v.y*v.y + v.z*v.z + v.w*v.w;
    #pragma unroll
    for (int o = 16; o; o >>= 1) ss += __shfl_xor_sync(0xffffffffu, ss, o);
    float inv = rsqrtf(ss);
    inv = inv * (1.5f - 0.5f * ss * inv * inv);
    v.x *= inv; v.y *= inv; v.z *= inv; v.w *= inv;
    ((float4*)xs[wid])[lane] = v;

    ((float4*)(g_xn + (size_t)row * DD))[lane] = v;

    __half h[4];
    h[0] = __float2half_rn(v.x); h[1] = __float2half_rn(v.y);
    h[2] = __float2half_rn(v.z); h[3] = __float2half_rn(v.w);
    *(ushort4*)(g_h + (size_t)row * DD + lane * 4) = *(ushort4*)h;

    float4 vs = make_float4(v.x * SCL, v.y * SCL, v.z * SCL, v.w * SCL);
    __nv_fp8x4_e4m3 p4(vs);
    *(uint32_t*)(g_f8 + (size_t)row * DD + lane * 4) = *(uint32_t*)&p4;

    if (lane == 0) {
        g_sumf[row] = 0.0f;
        g_nneg[row] = 0;
    }
    __syncthreads();

    int gl = wid & ~3;
    int self = wid & 3;
    float4 a = ((float4*)xs[wid])[lane];
    float p[4];
    #pragma unroll
    for (int m = 0; m < 4; m++) {
        float4 b = ((float4*)xs[gl + m])[lane];
        float d = a.x*b.x + a.y*b.y + a.z*b.z + a.w*b.w;
        #pragma unroll
        for (int o = 16; o; o >>= 1) d += __shfl_xor_sync(0xffffffffu, d, o);
        p[m] = d;
    }
    if (lane == 0) {
        float mn = 3.4e38f;
        #pragma unroll
        for (int m = 0; m < 4; m++) {
            if (m != self) {
                int slot = m - (m > self ? 1 : 0);
                g_pos[row * 3 + slot] = p[m];
                mn = fminf(mn, p[m]);
            }
        }
        g_minpos[row] = mn;
    }
    __syncthreads();

    if (wid < 4) {
        float4 s0 = ((float4*)xs[wid])[lane], s1 = ((float4*)xs[wid + 4])[lane];
        s0.x += s1.x; s0.y += s1.y; s0.z += s1.z; s0.w += s1.w;
        ((float4*)xs[wid])[lane] = s0;
    }
    __syncthreads();
    if (wid < 2) {
        float4 s0 = ((float4*)xs[wid])[lane], s1 = ((float4*)xs[wid + 2])[lane];
        s0.x += s1.x; s0.y += s1.y; s0.z += s1.z; s0.w += s1.w;
        ((float4*)xs[wid])[lane] = s0;
    }
    __syncthreads();
    if (wid == 0) {
        float4 s0 = ((float4*)xs[0])[lane], s1 = ((float4*)xs[1])[lane];
        s0.x += s1.x; s0.y += s1.y; s0.z += s1.z; s0.w += s1.w;
        ((float4*)(g_Spart + (size_t)blockIdx.x * DD))[lane] = s0;
    }
}

// ---------------- kernel 2: hybrid tensor/FFMA triangular sim ----------------
// smem union:
//   tensor path: fp8 A at 0 (18432), fp8 B at 18432
//   ffma  path: fp32 A [k][r] at 0 (65536), fp16 B [k][c] at 65536 (32768)
#define FF_A 0
#define FF_B 65536
#define SM_TOTAL (FF_B + TS * TS * 2)   // 98304 -> 2 CTAs/SM

extern "C" __global__ void __launch_bounds__(256, 2) sim_kernel() {
    int bid = blockIdx.x;
    int ti = (int)((129.0f - sqrtf((float)(16641 - 8 * bid))) * 0.5f);
    while (ti * NT - ti * (ti - 1) / 2 > bid) ti--;
    while ((ti + 1) * NT - (ti + 1) * ti / 2 <= bid) ti++;
    int tj = ti + (bid - (ti * NT - ti * (ti - 1) / 2));
    bool diag = (ti == tj);

    extern __shared__ char sh[];
    uint32_t sb = smem_u32(sh);
    int tid = threadIdx.x;
    int ibase = ti * TS, jbase = tj * TS;

    bool use_tensor = diag || (((bid * 9) & 15) < 10);

    if (use_tensor) {
        // ================= tensor (fp8 HMMA) path — R15 body =================
        int wid = tid >> 5, lane = tid & 31;
        int wm = wid >> 2, wn = wid & 3;

        {
            int r = tid >> 1, h = tid & 1;
            const uint4* sa  = (const uint4*)(g_f8 + (size_t)(ibase + r) * DD) + h * 4;
            const uint4* sbp = (const uint4*)(g_f8 + (size_t)(jbase + r) * DD) + h * 4;
            uint4* da = (uint4*)(sh + 0      + r * SROWB + h * 64);
            uint4* db = (uint4*)(sh + TILE8B + r * SROWB + h * 64);
            #pragma unroll
            for (int u = 0; u < 4; u++) { da[u] = sa[u]; db[u] = sbp[u]; }
        }
        __syncthreads();

        float c[4][4][4];
        #pragma unroll
        for (int mi = 0; mi < 4; mi++)
            #pragma unroll
            for (int ni = 0; ni < 4; ni++)
                #pragma unroll
                for (int e = 0; e < 4; e++) c[mi][ni][e] = 0.0f;

        int a_row_add = (lane & 7) + ((lane >> 3) & 1) * 8;
        int a_k_add   = (lane >> 4) * 16;
        int b_row_add = (lane & 7) + (lane >> 4) * 8;
        int b_k_add   = ((lane >> 3) & 1) * 16;
        uint32_t a_b = sb + 0, b_b = sb + TILE8B;

        #pragma unroll
        for (int k0 = 0; k0 < 4; k0++) {
            int kb = k0 * 32;
            uint32_t ah[4][4], bh[4][2];
            #pragma unroll
            for (int mi = 0; mi < 4; mi++) {
                uint32_t off = (uint32_t)((wm * 64 + mi * 16 + a_row_add) * SROWB + kb + a_k_add);
                ldsm4(ah[mi], a_b + off);
            }
            #pragma unroll
            for (int n2 = 0; n2 < 2; n2++) {
                uint32_t off = (uint32_t)((wn * 32 + n2 * 16 + b_row_add) * SROWB + kb + b_k_add);
                uint32_t t[4];
                ldsm4(t, b_b + off);
                bh[n2*2][0] = t[0]; bh[n2*2][1] = t[1];
                bh[n2*2+1][0] = t[2]; bh[n2*2+1][1] = t[3];
            }
            #pragma unroll
            for (int mi = 0; mi < 4; mi++)
                #pragma unroll
                for (int ni = 0; ni < 4; ni++)
                    mma16832f8(c[mi][ni], ah[mi], bh[ni]);
        }

        int g = lane >> 2, q = lane & 3;
        float thr[4][2], thc[4][2];
        #pragma unroll
        for (int mi = 0; mi < 4; mi++) {
            thr[mi][0] = (g_minpos[ibase + wm*64 + mi*16 + g]     - 0.05f) * 64.0f;
            thr[mi][1] = (g_minpos[ibase + wm*64 + mi*16 + g + 8] - 0.05f) * 64.0f;
        }
        #pragma unroll
        for (int ni = 0; ni < 4; ni++) {
            thc[ni][0] = (g_minpos[jbase + wn*32 + ni*8 + q*2]     - 0.05f) * 64.0f;
            thc[ni][1] = (g_minpos[jbase + wn*32 + ni*8 + q*2 + 1] - 0.05f) * 64.0f;
        }

        float rf[4][2], rc[4][2], cf[4][2], cc[4][2];
        #pragma unroll
        for (int a = 0; a < 4; a++)
            #pragma unroll
            for (int b = 0; b < 2; b++) {
                rf[a][b] = 0.f; rc[a][b] = 0.f; cf[a][b] = 0.f; cc[a][b] = 0.f;
            }

        if (!diag) {
            #pragma unroll
            for (int mi = 0; mi < 4; mi++)
                #pragma unroll
                for (int ni = 0; ni < 4; ni++)
                    #pragma unroll
                    for (int h = 0; h < 2; h++)
                        #pragma unroll
                        for (int p = 0; p < 2; p++) {
                            float s = c[mi][ni][h*2 + p];
                            float f = fexp20s(s);
                            if (s > thr[mi][h]) { rf[mi][h] += f; rc[mi][h] += 1.0f; }
                            if (s > thc[ni][p]) { cf[ni][p] += f; cc[ni][p] += 1.0f; }
                        }
        } else {
            int gi[4][2];
            #pragma unroll
            for (int mi = 0; mi < 4; mi++) {
                gi[mi][0] = (ibase + wm*64 + mi*16 + g) >> 2;
                gi[mi][1] = (ibase + wm*64 + mi*16 + g + 8) >> 2;
            }
            #pragma unroll
            for (int mi = 0; mi < 4; mi++)
                #pragma unroll
                for (int ni = 0; ni < 4; ni++)
                    #pragma unroll
                    for (int h = 0; h < 2; h++)
                        #pragma unroll
                        for (int p = 0; p < 2; p++) {
                            float s = c[mi][ni][h*2 + p];
                            float f = fexp20s(s);
                            int j = jbase + wn*32 + ni*8 + q*2 + p;
                            if ((j >> 2) != gi[mi][h] && s > thr[mi][h]) {
                                rf[mi][h] += f;
                                rc[mi][h] += 1.0f;
                            }
                        }
        }

        #pragma unroll
        for (int mi = 0; mi < 4; mi++)
            #pragma unroll
            for (int h = 0; h < 2; h++) {
                #pragma unroll
                for (int o = 1; o <= 2; o <<= 1) {
                    rf[mi][h] += __shfl_xor_sync(0xffffffffu, rf[mi][h], o);
                    rc[mi][h] += __shfl_xor_sync(0xffffffffu, rc[mi][h], o);
                }
            }
        if (!diag) {
            #pragma unroll
            for (int ni = 0; ni < 4; ni++)
                #pragma unroll
                for (int p = 0; p < 2; p++) {
                    #pragma unroll
                    for (int o = 4; o <= 16; o <<= 1) {
                        cf[ni][p] += __shfl_xor_sync(0xffffffffu, cf[ni][p], o);
                        cc[ni][p] += __shfl_xor_sync(0xffffffffu, cc[ni][p], o);
                    }
                }
        }

        __syncthreads();
        float2* rowst = (float2*)sh;
        float2* colst = (float2*)(sh + 4096);
        if (q == 0) {
            #pragma unroll
            for (int mi = 0; mi < 4; mi++)
                #pragma unroll
                for (int h = 0; h < 2; h++) {
                    int rl = wm*64 + mi*16 + g + h*8;
                    rowst[wn*128 + rl] = make_float2(rf[mi][h], rc[mi][h]);
                }
        }
        if (!diag && g == 0) {
            #pragma unroll
            for (int ni = 0; ni < 4; ni++)
                #pragma unroll
                for (int p = 0; p < 2; p++) {
                    int cl = wn*32 + ni*8 + q*2 + p;
                    colst[wm*128 + cl] = make_float2(cf[ni][p], cc[ni][p]);
                }
        }
        __syncthreads();

        if (tid < 128) {
            float2 e = rowst[tid];
            #pragma unroll
            for (int w = 1; w < 4; w++) {
                float2 o = rowst[w*128 + tid];
                e.x += o.x; e.y += o.y;
            }
            int i = ibase + tid;
            atomicAdd(&g_sumf[i], e.x);
            atomicAdd(&g_nneg[i], (int)e.y);
        } else if (!diag) {
            int cidx = tid - 128;
            float2 e = colst[cidx];
            float2 o = colst[128 + cidx];
            e.x += o.x; e.y += o.y;
            int j = jbase + cidx;
            atomicAdd(&g_sumf[j], e.x);
            atomicAdd(&g_nneg[j], (int)e.y);
        }
    } else {
        // ================= FFMA (f32x2) path — never sees diag tiles =================
        int tx = tid & 15, ty = tid >> 4;
        float* As = (float*)(sh + FF_A);          // [k][r] fp32
        __half* Bs = (__half*)(sh + FF_B);        // [k][c] fp16

        // fill: thread -> row/col tid>>1, k-half tid&1
        {
            int r = tid >> 1, hh = tid & 1;
            const float4* sa = (const float4*)(g_xn + (size_t)(ibase + r) * DD) + hh * 16;
            #pragma unroll
            for (int u = 0; u < 16; u++) {
                float4 v = sa[u];
                int k = hh * 64 + u * 4;
                As[(k+0)*TS + r] = v.x;
                As[(k+1)*TS + r] = v.y;
                As[(k+2)*TS + r] = v.z;
                As[(k+3)*TS + r] = v.w;
            }
            const ushort4* sbp = (const ushort4*)(g_h + (size_t)(jbase + r) * DD) + hh * 16;
            #pragma unroll
            for (int u = 0; u < 16; u++) {
                ushort4 v = sbp[u];
                int k = hh * 64 + u * 4;
                *(uint16_t*)(Bs + (k+0)*TS + r) = v.x;
                *(uint16_t*)(Bs + (k+1)*TS + r) = v.y;
                *(uint16_t*)(Bs + (k+2)*TS + r) = v.z;
                *(uint16_t*)(Bs + (k+3)*TS + r) = v.w;
            }
        }
        __syncthreads();

        ull acc[2][4][4];
        #pragma unroll
        for (int a = 0; a < 2; a++)
            #pragma unroll
            for (int b = 0; b < 4; b++)
                #pragma unroll
                for (int e = 0; e < 4; e++) acc[a][b][e] = 0ull;

        #pragma unroll 4
        for (int k = 0; k < DD; k++) {
            const float* ap = As + k * TS;
            float4 a0 = *(const float4*)(ap + ty * 4);
            float4 a1 = *(const float4*)(ap + 64 + ty * 4);
            const __half2* bp = (const __half2*)(Bs + k * TS);
            float2 f0 = __half22float2(bp[tx*2]);
            float2 f1 = __half22float2(bp[tx*2 + 1]);
            float2 f2 = __half22float2(bp[32 + tx*2]);
            float2 f3 = __half22float2(bp[32 + tx*2 + 1]);
            ull bb0 = pk(f0.x, f0.y), bb1 = pk(f1.x, f1.y);
            ull bb2 = pk(f2.x, f2.y), bb3 = pk(f3.x, f3.y);
            float aa[8] = {a0.x, a0.y, a0.z, a0.w, a1.x, a1.y, a1.z, a1.w};
            #pragma unroll
            for (int rh = 0; rh < 2; rh++) {
                #pragma unroll
                for (int u = 0; u < 4; u++) {
                    float av = aa[rh*4 + u];
                    ull ar = pk(av, av);
                    fma2(acc[rh][u][0], ar, bb0);
                    fma2(acc[rh][u][1], ar, bb1);
                    fma2(acc[rh][u][2], ar, bb2);
                    fma2(acc[rh][u][3], ar, bb3);
                }
            }
        }

        // epilogue
        int i0 = ibase + ty * 4;
        int j0 = jbase + tx * 4;
        float thr[2][4], thc[2][4];
        #pragma unroll
        for (int rh = 0; rh < 2; rh++)
            #pragma unroll
            for (int u = 0; u < 4; u++)
                thr[rh][u] = g_minpos[i0 + rh*64 + u] - 0.05f;
        #pragma unroll
        for (int ch = 0; ch < 2; ch++)
            #pragma unroll
            for (int v = 0; v < 4; v++)
                thc[ch][v] = g_minpos[j0 + ch*64 + v] - 0.05f;

        float rf[2][4], rc[2][4], cf[2][4], cc[2][4];
        #pragma unroll
        for (int a = 0; a < 2; a++)
            #pragma unroll
            for (int b = 0; b < 4; b++) {
                rf[a][b] = 0.f; rc[a][b] = 0.f; cf[a][b] = 0.f; cc[a][b] = 0.f;
            }

        #pragma unroll
        for (int rh = 0; rh < 2; rh++) {
            #pragma unroll
            for (int u = 0; u < 4; u++) {
                #pragma unroll
                for (int ch = 0; ch < 2; ch++) {
                    float2 p0 = upk(acc[rh][u][ch*2 + 0]);
                    float2 p1 = upk(acc[rh][u][ch*2 + 1]);
                    float sv[4] = {p0.x, p0.y, p1.x, p1.y};
                    #pragma unroll
                    for (int v = 0; v < 4; v++) {
                        float s = sv[v];
                        float f = fexp20(s);
                        if (s > thr[rh][u]) { rf[rh][u] += f; rc[rh][u] += 1.0f; }
                        if (s > thc[ch][v]) { cf[ch][v] += f; cc[ch][v] += 1.0f; }
                    }
                }
            }
        }

        // row reduce across tx (16-lane groups within warp)
        #pragma unroll
        for (int rh = 0; rh < 2; rh++)
            #pragma unroll
            for (int u = 0; u < 4; u++) {
                #pragma unroll
                for (int o = 8; o; o >>= 1) {
                    rf[rh][u] += __shfl_xor_sync(0xffffffffu, rf[rh][u], o);
                    rc[rh][u] += __shfl_xor_sync(0xffffffffu, rc[rh][u], o);
                }
                if (tx == 0) {
                    int i = i0 + rh*64 + u;
                    atomicAdd(&g_sumf[i], rf[rh][u]);
                    atomicAdd(&g_nneg[i], (int)rc[rh][u]);
                }
            }

        // col reduce across ty via smem staging (tiles dead after sync)
        __syncthreads();
        float2* colst = (float2*)sh;   // [16 ty][128 cols] = 16KB
        #pragma unroll
        for (int ch = 0; ch < 2; ch++)
            #pragma unroll
            for (int v = 0; v < 4; v++) {
                int cl = ch*64 + tx*4 + v;
                colst[ty*128 + cl] = make_float2(cf[ch][v], cc[ch][v]);
            }
        __syncthreads();
        if (tid < 128) {
            float fsum = 0.f, csum = 0.f;
            #pragma unroll
            for (int t = 0; t < 16; t++) {
                float2 e = colst[t*128 + tid];
                fsum += e.x; csum += e.y;
            }
            int j = jbase + tid;
            atomicAdd(&g_sumf[j], fsum);
            atomicAdd(&g_nneg[j], (int)csum);
        }
    }
}

// ---------------- kernel 3: finalize ----------------
__global__ void finalize_kernel(float* __restrict__ out) {
    __shared__ double sdd[1024];
    int tid = threadIdx.x;

    {
        int c = tid & 127, ch = tid >> 7;
        double s = 0.0;
        for (int b = ch * 128; b < ch * 128 + 128; b++)
            s += (double)g_Spart[b * DD + c];
        sdd[tid] = s;
    }
    __syncthreads();
    double sq = 0.0;
    if (tid < 128) {
        double s = 0.0;
        #pragma unroll
        for (int ch = 0; ch < 8; ch++) s += sdd[ch * 128 + tid];
        sq = s * s;
    }
    __syncthreads();
    sdd[tid] = sq;
    __syncthreads();
    for (int s = 512; s; s >>= 1) {
        if (tid < s) sdd[tid] += sdd[tid + s];
        __syncthreads();
    }
    double S2 = sdd[0];
    __syncthreads();

    const float base = 0.9f;

    double l = 0.0, pr = 0.0, pd = 0.0;
    for (int i = tid; i < NN; i += 1024) {
        float p0 = g_pos[i*3+0], p1 = g_pos[i*3+1], p2 = g_pos[i*3+2];
        int np = 0; float pm = 0.0f;
        if (p0 < base) { pm += log1pf(__expf(-2.0f * (p0 - 0.5f))); np++; }
        if (p1 < base) { pm += log1pf(__expf(-2.0f * (p1 - 0.5f))); np++; }
        if (p2 < base) { pm += log1pf(__expf(-2.0f * (p2 - 0.5f))); np++; }
        float pos_loss = (np > 0) ? (pm / (float)np)
                                  : log1pf(__expf(-2.0f * (g_minpos[i] - 0.5f)));
        int nn = g_nneg[i];
        float negm = g_sumf[i] / (float)max(nn, 1);
        l  += (double)(pos_loss + 0.1f * negm);
        pr += (nn == 0) ? 1.0 : 0.0;
        pd += (double)p0 + (double)p1 + (double)p2;
    }

    double vals[3] = {l, pr, pd};
    double res[3];
    #pragma unroll
    for (int v = 0; v < 3; v++) {
        sdd[tid] = vals[v];
        __syncthreads();
        for (int s = 512; s; s >>= 1) {
            if (tid < s) sdd[tid] += sdd[tid + s];
            __syncthreads();
        }
        res[v] = sdd[0];
        __syncthreads();
    }
    if (tid == 0) {
        out[0] = (float)(res[0] / (double)NN);
        out[1] = (float)(res[1] / (double)NN);
        out[2] = (float)(res[2] / ((double)NN * 3.0));
        out[3] = (float)((S2 - (double)NN - res[2]) /
                         ((double)NN * (double)(NN - 4)));
    }
}

// ---------------- launcher ----------------
extern "C" void kernel_launch(void* const* d_in, const int* in_sizes, int n_in,
                              void* d_out, int out_size) {
    const float* x = (const float*)d_in[0];
    float* out = (float*)d_out;

    cudaFuncSetAttribute(sim_kernel, cudaFuncAttributeMaxDynamicSharedMemorySize, SM_TOTAL);

    prep_kernel<<<NN / 8, 256>>>(x);
    sim_kernel<<<NTILES, 256, SM_TOTAL>>>();
    finalize_kernel<<<1, 1024>>>(out);
}

// round 17
// speedup vs baseline: 1.5526x; 1.5526x over previous
#include <cuda_runtime.h>
#include <cuda_fp8.h>
#include <math.h>
#include <stdint.h>

#define NN 8192
#define DD 128
#define TS 128
#define NT (NN / TS)        // 64
#define SROWB 144           // fp8 tile row stride (128 + 16 pad -> conflict-free)
#define TILEB (TS * SROWB)  // 18432
#define NBLK (NN / 8)
#define SCL 8.0f            // fp8 pre-scale; sims come out x64

// ---------------- device scratch ----------------
__device__ uint8_t g_f8[NN * DD];    // e4m3 normalized rows (x8)
__device__ float g_pos[NN * 3];
__device__ float g_minpos[NN];
__device__ float g_sumf[NN];
__device__ int   g_nneg[NN];
__device__ float g_Spart[NBLK * DD];

__device__ __forceinline__ uint32_t smem_u32(const void* p) {
    uint32_t a;
    asm("{ .reg .u64 t; cvta.to.shared.u64 t, %1; cvt.u32.u64 %0, t; }"
        : "=r"(a) : "l"(p));
    return a;
}

__device__ __forceinline__ void ldsm4(uint32_t r[4], uint32_t addr) {
    asm volatile("ldmatrix.sync.aligned.m8n8.x4.shared.b16 {%0,%1,%2,%3}, [%4];"
                 : "=r"(r[0]), "=r"(r[1]), "=r"(r[2]), "=r"(r[3]) : "r"(addr));
}

__device__ __forceinline__ void mma16832f8(float c[4], const uint32_t a[4],
                                           const uint32_t b[2]) {
    asm volatile(
        "mma.sync.aligned.m16n8k32.row.col.f32.e4m3.e4m3.f32 "
        "{%0,%1,%2,%3},{%4,%5,%6,%7},{%8,%9},{%0,%1,%2,%3};"
        : "+f"(c[0]), "+f"(c[1]), "+f"(c[2]), "+f"(c[3])
        : "r"(a[0]), "r"(a[1]), "r"(a[2]), "r"(a[3]), "r"(b[0]), "r"(b[1]));
}

// f ~= exp(20*(s64/64) - 10) via Schraudolph; s64 is the x64-scaled sim.
__device__ __forceinline__ float fexp20s(float s64) {
    return __int_as_float((int)fmaf(3781938.5f, s64, 943844773.0f));
}

// ---------------- kernel 1: normalize + fp8 + positives + init + S partials ----------------
__global__ void prep_kernel(const float* __restrict__ x) {
    __shared__ float xs[8][128];
    int wid = threadIdx.x >> 5, lane = threadIdx.x & 31;
    int row = blockIdx.x * 8 + wid;

    float4 v = ((const float4*)(x + (size_t)row * DD))[lane];
    float ss = v.x*v.x + v.y*v.y + v.z*v.z + v.w*v.w;
    #pragma unroll
    for (int o = 16; o; o >>= 1) ss += __shfl_xor_sync(0xffffffffu, ss, o);
    float inv = rsqrtf(ss);
    inv = inv * (1.5f - 0.5f * ss * inv * inv);
    v.x *= inv; v.y *= inv; v.z *= inv; v.w *= inv;
    ((float4*)xs[wid])[lane] = v;

    float4 vs = make_float4(v.x * SCL, v.y * SCL, v.z * SCL, v.w * SCL);
    __nv_fp8x4_e4m3 p4(vs);
    *(uint32_t*)(g_f8 + (size_t)row * DD + lane * 4) = *(uint32_t*)&p4;

    if (lane == 0) {
        g_sumf[row] = 0.0f;
        g_nneg[row] = 0;
    }
    __syncthreads();

    // positives (fp32-exact)
    int gl = wid & ~3;
    int self = wid & 3;
    float4 a = ((float4*)xs[wid])[lane];
    float p[4];
    #pragma unroll
    for (int m = 0; m < 4; m++) {
        float4 b = ((float4*)xs[gl + m])[lane];
        float d = a.x*b.x + a.y*b.y + a.z*b.z + a.w*b.w;
        #pragma unroll
        for (int o = 16; o; o >>= 1) d += __shfl_xor_sync(0xffffffffu, d, o);
        p[m] = d;
    }
    if (lane == 0) {
        float mn = 3.4e38f;
        #pragma unroll
        for (int m = 0; m < 4; m++) {
            if (m != self) {
                int slot = m - (m > self ? 1 : 0);
                g_pos[row * 3 + slot] = p[m];
                mn = fminf(mn, p[m]);
            }
        }
        g_minpos[row] = mn;
    }
    __syncthreads();

    // block-sum of normalized rows -> g_Spart
    if (wid < 4) {
        float4 s0 = ((float4*)xs[wid])[lane], s1 = ((float4*)xs[wid + 4])[lane];
        s0.x += s1.x; s0.y += s1.y; s0.z += s1.z; s0.w += s1.w;
        ((float4*)xs[wid])[lane] = s0;
    }
    __syncthreads();
    if (wid < 2) {
        float4 s0 = ((float4*)xs[wid])[lane], s1 = ((float4*)xs[wid + 2])[lane];
        s0.x += s1.x; s0.y += s1.y; s0.z += s1.z; s0.w += s1.w;
        ((float4*)xs[wid])[lane] = s0;
    }
    __syncthreads();
    if (wid == 0) {
        float4 s0 = ((float4*)xs[0])[lane], s1 = ((float4*)xs[1])[lane];
        s0.x += s1.x; s0.y += s1.y; s0.z += s1.z; s0.w += s1.w;
        ((float4*)(g_Spart + (size_t)blockIdx.x * DD))[lane] = s0;
    }
}

// ---------------- kernel 2: fp8 MMA, one CTA = one A tile x two B tiles ----------------
#define SM_A  0
#define SM_B0 TILEB
#define SM_B1 (2 * TILEB)
#define SM_ST (3 * TILEB)                  // col staging (2KB)
#define SM_TOTAL (SM_ST + 2048)            // 57344 -> 2 CTAs/SM

extern "C" __global__ void __launch_bounds__(256, 2) sim_kernel() {
    int ti = blockIdx.y;
    int tj0 = blockIdx.x * 2;
    if (tj0 + 1 < ti) return;              // both sub-tiles below diagonal

    extern __shared__ char sh[];
    uint32_t sb = smem_u32(sh);
    int tid = threadIdx.x;
    int wid = tid >> 5, lane = tid & 31;
    int wm = wid >> 2, wn = wid & 3;       // warp grid 2 x 4 (64 x 32 per warp)
    int ibase = ti * TS;

    // ---- load A + both B tiles upfront ----
    {
        int r = tid >> 1, h = tid & 1;
        const uint4* sa = (const uint4*)(g_f8 + (size_t)(ibase + r) * DD) + h * 4;
        uint4* da = (uint4*)(sh + SM_A + r * SROWB + h * 64);
        #pragma unroll
        for (int u = 0; u < 4; u++) da[u] = sa[u];
        if (tj0 >= ti) {
            const uint4* s0 = (const uint4*)(g_f8 + (size_t)(tj0 * TS + r) * DD) + h * 4;
            uint4* d0 = (uint4*)(sh + SM_B0 + r * SROWB + h * 64);
            #pragma unroll
            for (int u = 0; u < 4; u++) d0[u] = s0[u];
        }
        const uint4* s1 = (const uint4*)(g_f8 + (size_t)((tj0 + 1) * TS + r) * DD) + h * 4;
        uint4* d1 = (uint4*)(sh + SM_B1 + r * SROWB + h * 64);
        #pragma unroll
        for (int u = 0; u < 4; u++) d1[u] = s1[u];
    }
    __syncthreads();

    // row thresholds + persistent row stats
    int g = lane >> 2, q = lane & 3;
    float thr[4][2];
    int   gi[4][2];
    #pragma unroll
    for (int mi = 0; mi < 4; mi++) {
        int r0 = ibase + wm*64 + mi*16 + g;
        thr[mi][0] = (g_minpos[r0]     - 0.05f) * 64.0f;
        thr[mi][1] = (g_minpos[r0 + 8] - 0.05f) * 64.0f;
        gi[mi][0] = r0 >> 2;
        gi[mi][1] = (r0 + 8) >> 2;
    }
    float rf[4][2], rc[4][2];
    #pragma unroll
    for (int a = 0; a < 4; a++)
        #pragma unroll
        for (int b = 0; b < 2; b++) { rf[a][b] = 0.f; rc[a][b] = 0.f; }

    int a_row_add = (lane & 7) + ((lane >> 3) & 1) * 8;
    int a_k_add   = (lane >> 4) * 16;
    int b_row_add = (lane & 7) + (lane >> 4) * 8;
    int b_k_add   = ((lane >> 3) & 1) * 16;
    uint32_t a_b = sb + SM_A;
    float2* colst = (float2*)(sh + SM_ST);   // [2 wm][128 cols]

    for (int t = 0; t < 2; t++) {
        int tj = tj0 + t;
        if (tj < ti) continue;
        bool diag = (tj == ti);
        int jbase = tj * TS;
        uint32_t b_b = sb + (t ? SM_B1 : SM_B0);

        // ---- MMA ----
        float c[4][4][4];
        #pragma unroll
        for (int mi = 0; mi < 4; mi++)
            #pragma unroll
            for (int ni = 0; ni < 4; ni++)
                #pragma unroll
                for (int e = 0; e < 4; e++) c[mi][ni][e] = 0.0f;

        #pragma unroll
        for (int k0 = 0; k0 < 4; k0++) {
            int kb = k0 * 32;
            uint32_t ah[4][4], bh[4][2];
            #pragma unroll
            for (int mi = 0; mi < 4; mi++) {
                uint32_t off = (uint32_t)((wm*64 + mi*16 + a_row_add) * SROWB + kb + a_k_add);
                ldsm4(ah[mi], a_b + off);
            }
            #pragma unroll
            for (int n2 = 0; n2 < 2; n2++) {
                uint32_t off = (uint32_t)((wn*32 + n2*16 + b_row_add) * SROWB + kb + b_k_add);
                uint32_t tt[4];
                ldsm4(tt, b_b + off);
                bh[n2*2][0] = tt[0]; bh[n2*2][1] = tt[1];
                bh[n2*2+1][0] = tt[2]; bh[n2*2+1][1] = tt[3];
            }
            #pragma unroll
            for (int mi = 0; mi < 4; mi++)
                #pragma unroll
                for (int ni = 0; ni < 4; ni++)
                    mma16832f8(c[mi][ni], ah[mi], bh[ni]);
        }

        // ---- epilogue ----
        float thc[4][2];
        #pragma unroll
        for (int ni = 0; ni < 4; ni++) {
            thc[ni][0] = (g_minpos[jbase + wn*32 + ni*8 + q*2]     - 0.05f) * 64.0f;
            thc[ni][1] = (g_minpos[jbase + wn*32 + ni*8 + q*2 + 1] - 0.05f) * 64.0f;
        }
        float cf[4][2], cc[4][2];
        #pragma unroll
        for (int a = 0; a < 4; a++)
            #pragma unroll
            for (int b = 0; b < 2; b++) { cf[a][b] = 0.f; cc[a][b] = 0.f; }

        if (!diag) {
            #pragma unroll
            for (int mi = 0; mi < 4; mi++)
                #pragma unroll
                for (int ni = 0; ni < 4; ni++)
                    #pragma unroll
                    for (int h = 0; h < 2; h++)
                        #pragma unroll
                        for (int p = 0; p < 2; p++) {
                            float s = c[mi][ni][h*2 + p];
                            float f = fexp20s(s);
                            if (s > thr[mi][h]) { rf[mi][h] += f; rc[mi][h] += 1.0f; }
                            if (s > thc[ni][p]) { cf[ni][p] += f; cc[ni][p] += 1.0f; }
                        }
        } else {
            #pragma unroll
            for (int mi = 0; mi < 4; mi++)
                #pragma unroll
                for (int ni = 0; ni < 4; ni++)
                    #pragma unroll
                    for (int h = 0; h < 2; h++)
                        #pragma unroll
                        for (int p = 0; p < 2; p++) {
                            float s = c[mi][ni][h*2 + p];
                            float f = fexp20s(s);
                            int j = jbase + wn*32 + ni*8 + q*2 + p;
                            if ((j >> 2) != gi[mi][h] && s > thr[mi][h]) {
                                rf[mi][h] += f;
                                rc[mi][h] += 1.0f;
                            }
                        }
        }

        // ---- col reduce + atomics (per sub-tile) ----
        if (!diag) {
            #pragma unroll
            for (int ni = 0; ni < 4; ni++)
                #pragma unroll
                for (int p = 0; p < 2; p++) {
                    #pragma unroll
                    for (int o = 4; o <= 16; o <<= 1) {
                        cf[ni][p] += __shfl_xor_sync(0xffffffffu, cf[ni][p], o);
                        cc[ni][p] += __shfl_xor_sync(0xffffffffu, cc[ni][p], o);
                    }
                }
            __syncthreads();
            if (g == 0) {
                #pragma unroll
                for (int ni = 0; ni < 4; ni++)
                    #pragma unroll
                    for (int p = 0; p < 2; p++) {
                        int cl = wn*32 + ni*8 + q*2 + p;
                        colst[wm*128 + cl] = make_float2(cf[ni][p], cc[ni][p]);
                    }
            }
            __syncthreads();
            if (tid < 128) {
                float2 e = colst[tid];
                float2 o = colst[128 + tid];
                e.x += o.x; e.y += o.y;
                int j = jbase + tid;
                atomicAdd(&g_sumf[j], e.x);
                atomicAdd(&g_nneg[j], (int)e.y);
            }
        }
    }

    // ---- row flush (once per CTA) ----
    #pragma unroll
    for (int mi = 0; mi < 4; mi++)
        #pragma unroll
        for (int h = 0; h < 2; h++) {
            #pragma unroll
            for (int o = 1; o <= 2; o <<= 1) {
                rf[mi][h] += __shfl_xor_sync(0xffffffffu, rf[mi][h], o);
                rc[mi][h] += __shfl_xor_sync(0xffffffffu, rc[mi][h], o);
            }
        }
    __syncthreads();
    float2* rowst = (float2*)sh;   // tiles dead now
    if (q == 0) {
        #pragma unroll
        for (int mi = 0; mi < 4; mi++)
            #pragma unroll
            for (int h = 0; h < 2; h++) {
                int rl = wm*64 + mi*16 + g + h*8;
                rowst[wn*128 + rl] = make_float2(rf[mi][h], rc[mi][h]);
            }
    }
    __syncthreads();
    if (tid < 128) {
        float2 e = rowst[tid];
        #pragma unroll
        for (int w = 1; w < 4; w++) {
            float2 o = rowst[w*128 + tid];
            e.x += o.x; e.y += o.y;
        }
        int i = ibase + tid;
        atomicAdd(&g_sumf[i], e.x);
        atomicAdd(&g_nneg[i], (int)e.y);
    }
}

// ---------------- kernel 3: finalize (single block, 1024 threads) ----------------
__global__ void finalize_kernel(float* __restrict__ out) {
    __shared__ double sdd[1024];
    int tid = threadIdx.x;

    {
        int c = tid & 127, ch = tid >> 7;
        double s = 0.0;
        for (int b = ch * 128; b < ch * 128 + 128; b++)
            s += (double)g_Spart[b * DD + c];
        sdd[tid] = s;
    }
    __syncthreads();
    double sq = 0.0;
    if (tid < 128) {
        double s = 0.0;
        #pragma unroll
        for (int ch = 0; ch < 8; ch++) s += sdd[ch * 128 + tid];
        sq = s * s;
    }
    __syncthreads();
    sdd[tid] = sq;
    __syncthreads();
    for (int s = 512; s; s >>= 1) {
        if (tid < s) sdd[tid] += sdd[tid + s];
        __syncthreads();
    }
    double S2 = sdd[0];
    __syncthreads();

    const float base = 0.9f;   // sim.max() = self-sim 1.0 -> max(0.9, 0.7)

    double l = 0.0, pr = 0.0, pd = 0.0;
    for (int i = tid; i < NN; i += 1024) {
        float p0 = g_pos[i*3+0], p1 = g_pos[i*3+1], p2 = g_pos[i*3+2];
        int np = 0; float pm = 0.0f;
        if (p0 < base) { pm += log1pf(__expf(-2.0f * (p0 - 0.5f))); np++; }
        if (p1 < base) { pm += log1pf(__expf(-2.0f * (p1 - 0.5f))); np++; }
        if (p2 < base) { pm += log1pf(__expf(-2.0f * (p2 - 0.5f))); np++; }
        float pos_loss = (np > 0) ? (pm / (float)np)
                                  : log1pf(__expf(-2.0f * (g_minpos[i] - 0.5f)));
        int nn = g_nneg[i];
        float negm = g_sumf[i] / (float)max(nn, 1);
        l  += (double)(pos_loss + 0.1f * negm);
        pr += (nn == 0) ? 1.0 : 0.0;
        pd += (double)p0 + (double)p1 + (double)p2;
    }

    double vals[3] = {l, pr, pd};
    double res[3];
    #pragma unroll
    for (int v = 0; v < 3; v++) {
        sdd[tid] = vals[v];
        __syncthreads();
        for (int s = 512; s; s >>= 1) {
            if (tid < s) sdd[tid] += sdd[tid + s];
            __syncthreads();
        }
        res[v] = sdd[0];
        __syncthreads();
    }
    if (tid == 0) {
        out[0] = (float)(res[0] / (double)NN);
        out[1] = (float)(res[1] / (double)NN);
        out[2] = (float)(res[2] / ((double)NN * 3.0));
        out[3] = (float)((S2 - (double)NN - res[2]) /
                         ((double)NN * (double)(NN - 4)));
    }
}

// ---------------- launcher ----------------
extern "C" void kernel_launch(void* const* d_in, const int* in_sizes, int n_in,
                              void* d_out, int out_size) {
    const float* x = (const float*)d_in[0];
    float* out = (float*)d_out;

    cudaFuncSetAttribute(sim_kernel, cudaFuncAttributeMaxDynamicSharedMemorySize, SM_TOTAL);

    prep_kernel<<<NN / 8, 256>>>(x);
    dim3 grid(NT / 2, NT);
    sim_kernel<<<grid, 256, SM_TOTAL>>>();
    finalize_kernel<<<1, 1024>>>(out);
}